// round 1
// baseline (speedup 1.0000x reference)
#include <cuda_runtime.h>
#include <math_constants.h>

// ----- problem constants -----
#define B_       16
#define HID_     2048
#define NH_      16
#define NKV_     8
#define HD_      128
#define BLK_     16
#define MAXB_    256
#define QSZ_     2048   // NH*HD
#define KVSZ_    1024   // NKV*HD
#define QKVSZ_   4096
#define LMAX_    4096   // MAXB*BLK
#define NSPLIT_  8
#define CHUNK_   512    // LMAX/NSPLIT
#define SCALE_   0.08838834764831845f  // 128^-0.5
#define EPS_     1e-6f

// ----- scratch (device globals; no allocation allowed) -----
__device__ float g_qkv [B_ * QKVSZ_];
__device__ float g_q   [B_ * NH_  * HD_];
__device__ float g_k   [B_ * NKV_ * HD_];
__device__ float g_v   [B_ * NKV_ * HD_];
__device__ float g_pmax[B_ * NH_ * NSPLIT_];
__device__ float g_psum[B_ * NH_ * NSPLIT_];
__device__ float g_pacc[B_ * NH_ * NSPLIT_ * HD_];
__device__ float g_attn[B_ * QSZ_];

// =====================================================================
// Kernel 1: QKV projection.  qkv[b,o] = hidden[b,:] . qkv_w[o,:]
// one block per output row o (4096 blocks); w row streamed once.
// =====================================================================
__global__ void k_qkv_gemv(const float* __restrict__ hs,
                           const float* __restrict__ w) {
    const int o   = blockIdx.x;
    const int tid = threadIdx.x;  // 128 threads
    const float4* wr = reinterpret_cast<const float4*>(w + (size_t)o * HID_);
    float acc[B_];
#pragma unroll
    for (int b = 0; b < B_; b++) acc[b] = 0.f;
    for (int j = tid; j < HID_ / 4; j += 128) {
        float4 w4 = wr[j];
#pragma unroll
        for (int b = 0; b < B_; b++) {
            float4 h4 = reinterpret_cast<const float4*>(hs + b * HID_)[j];
            acc[b] += w4.x * h4.x + w4.y * h4.y + w4.z * h4.z + w4.w * h4.w;
        }
    }
    __shared__ float red[4][B_];
    const int lane = tid & 31, wrp = tid >> 5;
#pragma unroll
    for (int b = 0; b < B_; b++) {
        float v = acc[b];
#pragma unroll
        for (int off = 16; off; off >>= 1) v += __shfl_xor_sync(0xffffffffu, v, off);
        if (lane == 0) red[wrp][b] = v;
    }
    __syncthreads();
    if (tid < B_)
        g_qkv[(size_t)tid * QKVSZ_ + o] =
            red[0][tid] + red[1][tid] + red[2][tid] + red[3][tid];
}

// =====================================================================
// Kernel 2: per-head RMSNorm (q,k) + RoPE (q,k) + scatter into scratch.
// grid (32, B): hh 0..15 -> q heads, 16..23 -> k heads, 24..31 -> v copy
// =====================================================================
__global__ void k_norm_rope(const float* __restrict__ qnw,
                            const float* __restrict__ knw,
                            const float* __restrict__ cs_cache,
                            const int*   __restrict__ positions) {
    const int hh = blockIdx.x, b = blockIdx.y, tid = threadIdx.x; // 128 threads
    float x;
    float* dst;
    const float* nw = nullptr;
    if (hh < NH_) {
        x = g_qkv[b * QKVSZ_ + hh * HD_ + tid];
        dst = g_q + (b * NH_ + hh) * HD_;  nw = qnw;
    } else if (hh < NH_ + NKV_) {
        int k = hh - NH_;
        x = g_qkv[b * QKVSZ_ + QSZ_ + k * HD_ + tid];
        dst = g_k + (b * NKV_ + k) * HD_;  nw = knw;
    } else {
        int k = hh - NH_ - NKV_;
        x = g_qkv[b * QKVSZ_ + QSZ_ + KVSZ_ + k * HD_ + tid];
        dst = g_v + (b * NKV_ + k) * HD_;
    }
    if (nw) {
        // RMSNorm over 128 elems
        float ss = x * x;
#pragma unroll
        for (int off = 16; off; off >>= 1) ss += __shfl_xor_sync(0xffffffffu, ss, off);
        __shared__ float sred[4];
        if ((tid & 31) == 0) sred[tid >> 5] = ss;
        __syncthreads();
        float tot = sred[0] + sred[1] + sred[2] + sred[3];
        x = x * rsqrtf(tot * (1.f / HD_) + EPS_) * nw[tid];
        // RoPE (half-split convention)
        __shared__ float xs[HD_];
        xs[tid] = x;
        __syncthreads();
        const float* cs = cs_cache + (size_t)positions[b] * HD_;
        if (tid < 64) x = x * cs[tid]      - xs[tid + 64] * cs[tid + 64];
        else          x = x * cs[tid - 64] + xs[tid - 64] * cs[tid];
    }
    dst[tid] = x;
}

// =====================================================================
// Kernel 3: split-KV flash decode. grid (NSPLIT, NKV, B), 128 threads.
// Each warp processes one token at a time (float4 K/V per lane, HD=128).
// The 2 GQA q-heads share every K/V read. New token (t == ctx-1) comes
// from g_k/g_v scratch instead of the cache (we never mutate inputs).
// =====================================================================
__global__ void k_attn_split(const float* __restrict__ kc,
                             const float* __restrict__ vc,
                             const int*   __restrict__ btab,
                             const int*   __restrict__ ctx_lens) {
    const int s  = blockIdx.x, kv = blockIdx.y, b = blockIdx.z;
    const int tid = threadIdx.x, lane = tid & 31, wrp = tid >> 5;
    const int ctx   = ctx_lens[b];
    const int start = s * CHUNK_;
    const int end   = min(start + CHUNK_, ctx);

    const float4 q0 = reinterpret_cast<const float4*>(g_q + (b * NH_ + kv * 2    ) * HD_)[lane];
    const float4 q1 = reinterpret_cast<const float4*>(g_q + (b * NH_ + kv * 2 + 1) * HD_)[lane];

    float m0 = -CUDART_INF_F, m1 = -CUDART_INF_F, l0 = 0.f, l1 = 0.f;
    float a0[4] = {0, 0, 0, 0}, a1[4] = {0, 0, 0, 0};
    const int* btr = btab + b * MAXB_;

    for (int t = start + wrp; t < end; t += 4) {
        const float4 *kp, *vp;
        if (t == ctx - 1) {
            kp = reinterpret_cast<const float4*>(g_k + (b * NKV_ + kv) * HD_);
            vp = reinterpret_cast<const float4*>(g_v + (b * NKV_ + kv) * HD_);
        } else {
            int slot = btr[t >> 4] * BLK_ + (t & (BLK_ - 1));
            size_t off = ((size_t)slot * NKV_ + kv) * HD_;
            kp = reinterpret_cast<const float4*>(kc + off);
            vp = reinterpret_cast<const float4*>(vc + off);
        }
        float4 k4 = kp[lane];
        float s0 = q0.x * k4.x + q0.y * k4.y + q0.z * k4.z + q0.w * k4.w;
        float s1 = q1.x * k4.x + q1.y * k4.y + q1.z * k4.z + q1.w * k4.w;
#pragma unroll
        for (int off = 16; off; off >>= 1) {
            s0 += __shfl_xor_sync(0xffffffffu, s0, off);
            s1 += __shfl_xor_sync(0xffffffffu, s1, off);
        }
        s0 *= SCALE_;  s1 *= SCALE_;
        float nm0 = fmaxf(m0, s0), nm1 = fmaxf(m1, s1);
        float f0 = __expf(m0 - nm0), f1 = __expf(m1 - nm1);  // exp(-inf)=0 first iter
        float p0 = __expf(s0 - nm0), p1 = __expf(s1 - nm1);
        l0 = l0 * f0 + p0;   l1 = l1 * f1 + p1;
        float4 v4 = vp[lane];
        a0[0] = a0[0] * f0 + p0 * v4.x;  a1[0] = a1[0] * f1 + p1 * v4.x;
        a0[1] = a0[1] * f0 + p0 * v4.y;  a1[1] = a1[1] * f1 + p1 * v4.y;
        a0[2] = a0[2] * f0 + p0 * v4.z;  a1[2] = a1[2] * f1 + p1 * v4.z;
        a0[3] = a0[3] * f0 + p0 * v4.w;  a1[3] = a1[3] * f1 + p1 * v4.w;
        m0 = nm0;  m1 = nm1;
    }

    // combine the 4 warps
    __shared__ float sm[2][4], sl[2][4], sa[2][4][HD_];
    if (lane == 0) { sm[0][wrp] = m0; sm[1][wrp] = m1; sl[0][wrp] = l0; sl[1][wrp] = l1; }
#pragma unroll
    for (int j = 0; j < 4; j++) {
        sa[0][wrp][lane * 4 + j] = a0[j];
        sa[1][wrp][lane * 4 + j] = a1[j];
    }
    __syncthreads();
#pragma unroll
    for (int h = 0; h < 2; h++) {
        float M = fmaxf(fmaxf(sm[h][0], sm[h][1]), fmaxf(sm[h][2], sm[h][3]));
        float L = 0.f, A = 0.f;
#pragma unroll
        for (int wv = 0; wv < 4; wv++) {
            float mw = sm[h][wv];
            float f  = (mw == -CUDART_INF_F) ? 0.f : __expf(mw - M);
            L += sl[h][wv] * f;
            A += sa[h][wv][tid] * f;
        }
        int idx = ((b * NH_ + kv * 2 + h) * NSPLIT_ + s);
        g_pacc[(size_t)idx * HD_ + tid] = A;
        if (tid == 0) { g_pmax[idx] = M; g_psum[idx] = L; }
    }
}

// =====================================================================
// Kernel 4: combine splits -> g_attn[b, qh*HD + d]
// =====================================================================
__global__ void k_attn_combine() {
    const int bq = blockIdx.x;       // b*NH + qh
    const int tid = threadIdx.x;     // 128
    float M = -CUDART_INF_F;
#pragma unroll
    for (int s = 0; s < NSPLIT_; s++) M = fmaxf(M, g_pmax[bq * NSPLIT_ + s]);
    float L = 0.f, A = 0.f;
#pragma unroll
    for (int s = 0; s < NSPLIT_; s++) {
        float mw = g_pmax[bq * NSPLIT_ + s];
        float f  = (mw == -CUDART_INF_F) ? 0.f : __expf(mw - M);
        L += g_psum[bq * NSPLIT_ + s] * f;
        A += g_pacc[((size_t)bq * NSPLIT_ + s) * HD_ + tid] * f;
    }
    g_attn[bq * HD_ + tid] = A / L;  // ctx >= 1 so L > 0
}

// =====================================================================
// Kernel 5: output projection.  out[b,o] = attn[b,:] . o_w[o,:]
// =====================================================================
__global__ void k_oproj_gemv(const float* __restrict__ ow,
                             float* __restrict__ out) {
    const int o   = blockIdx.x;      // 2048 blocks
    const int tid = threadIdx.x;     // 128
    const float4* wr = reinterpret_cast<const float4*>(ow + (size_t)o * QSZ_);
    float acc[B_];
#pragma unroll
    for (int b = 0; b < B_; b++) acc[b] = 0.f;
    for (int j = tid; j < QSZ_ / 4; j += 128) {
        float4 w4 = wr[j];
#pragma unroll
        for (int b = 0; b < B_; b++) {
            float4 a4 = reinterpret_cast<const float4*>(g_attn + b * QSZ_)[j];
            acc[b] += w4.x * a4.x + w4.y * a4.y + w4.z * a4.z + w4.w * a4.w;
        }
    }
    __shared__ float red[4][B_];
    const int lane = tid & 31, wrp = tid >> 5;
#pragma unroll
    for (int b = 0; b < B_; b++) {
        float v = acc[b];
#pragma unroll
        for (int off = 16; off; off >>= 1) v += __shfl_xor_sync(0xffffffffu, v, off);
        if (lane == 0) red[wrp][b] = v;
    }
    __syncthreads();
    if (tid < B_)
        out[(size_t)tid * HID_ + o] =
            red[0][tid] + red[1][tid] + red[2][tid] + red[3][tid];
}

// =====================================================================
extern "C" void kernel_launch(void* const* d_in, const int* in_sizes, int n_in,
                              void* d_out, int out_size) {
    const float* hidden   = (const float*)d_in[0];
    const int*   positions= (const int*)  d_in[1];
    const float* qkv_w    = (const float*)d_in[2];
    const float* q_norm_w = (const float*)d_in[3];
    const float* k_norm_w = (const float*)d_in[4];
    const float* o_w      = (const float*)d_in[5];
    const float* cs_cache = (const float*)d_in[6];
    const float* k_cache  = (const float*)d_in[7];
    const float* v_cache  = (const float*)d_in[8];
    // d_in[9] = slot_mapping (derived internally, unused)
    const int*   btab     = (const int*)  d_in[10];
    const int*   ctx_lens = (const int*)  d_in[11];
    float* out = (float*)d_out;

    k_qkv_gemv<<<QKVSZ_, 128>>>(hidden, qkv_w);
    k_norm_rope<<<dim3(NH_ + 2 * NKV_, B_), 128>>>(q_norm_w, k_norm_w, cs_cache, positions);
    k_attn_split<<<dim3(NSPLIT_, NKV_, B_), 128>>>(k_cache, v_cache, btab, ctx_lens);
    k_attn_combine<<<B_ * NH_, 128>>>();
    k_oproj_gemv<<<HID_, 128>>>(o_w, out);
}

// round 2
// speedup vs baseline: 2.1367x; 2.1367x over previous
#include <cuda_runtime.h>
#include <math_constants.h>

// ----- problem constants -----
#define B_       16
#define HID_     2048
#define NH_      16
#define NKV_     8
#define HD_      128
#define BLK_     16
#define MAXB_    256
#define QSZ_     2048   // NH*HD
#define KVSZ_    1024   // NKV*HD
#define QKVSZ_   4096
#define LMAX_    4096   // MAXB*BLK
#define NSPLIT_  16
#define CHUNK_   256    // LMAX/NSPLIT
#define TB_      8      // tokens per warp per mainloop iteration
#define SCALE_   0.08838834764831845f  // 128^-0.5
#define EPS_     1e-6f

// ----- scratch (device globals; no allocation allowed) -----
__device__ float g_qkv [B_ * QKVSZ_];
__device__ float g_q   [B_ * NH_  * HD_];
__device__ float g_k   [B_ * NKV_ * HD_];
__device__ float g_v   [B_ * NKV_ * HD_];
__device__ float g_pmax[B_ * NH_ * NSPLIT_];
__device__ float g_psum[B_ * NH_ * NSPLIT_];
__device__ float g_pacc[B_ * NH_ * NSPLIT_ * HD_];
__device__ float g_attn[B_ * QSZ_];

// =====================================================================
// Kernel 1: QKV projection.  qkv[b,o] = hidden[b,:] . qkv_w[o,:]
// =====================================================================
__global__ void k_qkv_gemv(const float* __restrict__ hs,
                           const float* __restrict__ w) {
    const int o   = blockIdx.x;
    const int tid = threadIdx.x;  // 128 threads
    const float4* wr = reinterpret_cast<const float4*>(w + (size_t)o * HID_);
    float acc[B_];
#pragma unroll
    for (int b = 0; b < B_; b++) acc[b] = 0.f;
    for (int j = tid; j < HID_ / 4; j += 128) {
        float4 w4 = wr[j];
#pragma unroll
        for (int b = 0; b < B_; b++) {
            float4 h4 = reinterpret_cast<const float4*>(hs + b * HID_)[j];
            acc[b] += w4.x * h4.x + w4.y * h4.y + w4.z * h4.z + w4.w * h4.w;
        }
    }
    __shared__ float red[4][B_];
    const int lane = tid & 31, wrp = tid >> 5;
#pragma unroll
    for (int b = 0; b < B_; b++) {
        float v = acc[b];
#pragma unroll
        for (int off = 16; off; off >>= 1) v += __shfl_xor_sync(0xffffffffu, v, off);
        if (lane == 0) red[wrp][b] = v;
    }
    __syncthreads();
    if (tid < B_)
        g_qkv[(size_t)tid * QKVSZ_ + o] =
            red[0][tid] + red[1][tid] + red[2][tid] + red[3][tid];
}

// =====================================================================
// Kernel 2: per-head RMSNorm (q,k) + RoPE (q,k) + scatter into scratch.
// =====================================================================
__global__ void k_norm_rope(const float* __restrict__ qnw,
                            const float* __restrict__ knw,
                            const float* __restrict__ cs_cache,
                            const int*   __restrict__ positions) {
    const int hh = blockIdx.x, b = blockIdx.y, tid = threadIdx.x; // 128 threads
    float x;
    float* dst;
    const float* nw = nullptr;
    if (hh < NH_) {
        x = g_qkv[b * QKVSZ_ + hh * HD_ + tid];
        dst = g_q + (b * NH_ + hh) * HD_;  nw = qnw;
    } else if (hh < NH_ + NKV_) {
        int k = hh - NH_;
        x = g_qkv[b * QKVSZ_ + QSZ_ + k * HD_ + tid];
        dst = g_k + (b * NKV_ + k) * HD_;  nw = knw;
    } else {
        int k = hh - NH_ - NKV_;
        x = g_qkv[b * QKVSZ_ + QSZ_ + KVSZ_ + k * HD_ + tid];
        dst = g_v + (b * NKV_ + k) * HD_;
    }
    if (nw) {
        float ss = x * x;
#pragma unroll
        for (int off = 16; off; off >>= 1) ss += __shfl_xor_sync(0xffffffffu, ss, off);
        __shared__ float sred[4];
        if ((tid & 31) == 0) sred[tid >> 5] = ss;
        __syncthreads();
        float tot = sred[0] + sred[1] + sred[2] + sred[3];
        x = x * rsqrtf(tot * (1.f / HD_) + EPS_) * nw[tid];
        __shared__ float xs[HD_];
        xs[tid] = x;
        __syncthreads();
        const float* cs = cs_cache + (size_t)positions[b] * HD_;
        if (tid < 64) x = x * cs[tid]      - xs[tid + 64] * cs[tid + 64];
        else          x = x * cs[tid - 64] + xs[tid - 64] * cs[tid];
    }
    dst[tid] = x;
}

// =====================================================================
// Kernel 3: split-KV flash decode, batched TB_ tokens per warp.
// grid (NSPLIT, NKV, B), 128 threads. K and V float4 loads for all TB_
// tokens issued together (MLP=16) before any dependent compute, then
// one online-softmax rescale per batch.
// =====================================================================
__global__ void __launch_bounds__(128)
k_attn_split(const float* __restrict__ kc,
             const float* __restrict__ vc,
             const int*   __restrict__ btab,
             const int*   __restrict__ ctx_lens) {
    const int s  = blockIdx.x, kv = blockIdx.y, b = blockIdx.z;
    const int tid = threadIdx.x, lane = tid & 31, wrp = tid >> 5;
    const int ctx   = ctx_lens[b];
    const int start = s * CHUNK_;
    const int end   = min(start + CHUNK_, ctx);

    const float4 q0 = reinterpret_cast<const float4*>(g_q + (b * NH_ + kv * 2    ) * HD_)[lane];
    const float4 q1 = reinterpret_cast<const float4*>(g_q + (b * NH_ + kv * 2 + 1) * HD_)[lane];

    float m0 = -CUDART_INF_F, m1 = -CUDART_INF_F, l0 = 0.f, l1 = 0.f;
    float a0[4] = {0, 0, 0, 0}, a1[4] = {0, 0, 0, 0};
    const int* btr = btab + b * MAXB_;

    for (int base = start + wrp * TB_; base < end; base += 4 * TB_) {
        float4 k4[TB_], v4[TB_];
        float s0[TB_], s1[TB_];
        // issue all K and V loads for the batch up front
#pragma unroll
        for (int i = 0; i < TB_; i++) {
            int t = base + i;
            if (t < end) {
                const float4 *kp, *vp;
                if (t == ctx - 1) {
                    kp = reinterpret_cast<const float4*>(g_k + (b * NKV_ + kv) * HD_);
                    vp = reinterpret_cast<const float4*>(g_v + (b * NKV_ + kv) * HD_);
                } else {
                    int slot = btr[t >> 4] * BLK_ + (t & (BLK_ - 1));
                    size_t off = ((size_t)slot * NKV_ + kv) * HD_;
                    kp = reinterpret_cast<const float4*>(kc + off);
                    vp = reinterpret_cast<const float4*>(vc + off);
                }
                k4[i] = __ldcs(kp + lane);
                v4[i] = __ldcs(vp + lane);
            } else {
                k4[i] = make_float4(0.f, 0.f, 0.f, 0.f);
                v4[i] = make_float4(0.f, 0.f, 0.f, 0.f);
            }
        }
        // dot products
#pragma unroll
        for (int i = 0; i < TB_; i++) {
            s0[i] = q0.x * k4[i].x + q0.y * k4[i].y + q0.z * k4[i].z + q0.w * k4[i].w;
            s1[i] = q1.x * k4[i].x + q1.y * k4[i].y + q1.z * k4[i].z + q1.w * k4[i].w;
        }
        // warp reductions (interleaved across the batch for pipelining)
#pragma unroll
        for (int off = 16; off; off >>= 1) {
#pragma unroll
            for (int i = 0; i < TB_; i++) {
                s0[i] += __shfl_xor_sync(0xffffffffu, s0[i], off);
                s1[i] += __shfl_xor_sync(0xffffffffu, s1[i], off);
            }
        }
        float bm0 = -CUDART_INF_F, bm1 = -CUDART_INF_F;
#pragma unroll
        for (int i = 0; i < TB_; i++) {
            if (base + i < end) { s0[i] *= SCALE_; s1[i] *= SCALE_; }
            else                { s0[i] = -CUDART_INF_F; s1[i] = -CUDART_INF_F; }
            bm0 = fmaxf(bm0, s0[i]);
            bm1 = fmaxf(bm1, s1[i]);
        }
        // one rescale per batch
        float nm0 = fmaxf(m0, bm0), nm1 = fmaxf(m1, bm1);
        float f0 = __expf(m0 - nm0), f1 = __expf(m1 - nm1);  // exp(-inf)=0 first iter
        l0 *= f0;  l1 *= f1;
#pragma unroll
        for (int j = 0; j < 4; j++) { a0[j] *= f0; a1[j] *= f1; }
#pragma unroll
        for (int i = 0; i < TB_; i++) {
            float p0 = __expf(s0[i] - nm0);   // 0 for inactive tokens
            float p1 = __expf(s1[i] - nm1);
            l0 += p0;  l1 += p1;
            a0[0] += p0 * v4[i].x;  a1[0] += p1 * v4[i].x;
            a0[1] += p0 * v4[i].y;  a1[1] += p1 * v4[i].y;
            a0[2] += p0 * v4[i].z;  a1[2] += p1 * v4[i].z;
            a0[3] += p0 * v4[i].w;  a1[3] += p1 * v4[i].w;
        }
        m0 = nm0;  m1 = nm1;
    }

    // combine the 4 warps
    __shared__ float sm[2][4], sl[2][4], sa[2][4][HD_];
    if (lane == 0) { sm[0][wrp] = m0; sm[1][wrp] = m1; sl[0][wrp] = l0; sl[1][wrp] = l1; }
#pragma unroll
    for (int j = 0; j < 4; j++) {
        sa[0][wrp][lane * 4 + j] = a0[j];
        sa[1][wrp][lane * 4 + j] = a1[j];
    }
    __syncthreads();
#pragma unroll
    for (int h = 0; h < 2; h++) {
        float M = fmaxf(fmaxf(sm[h][0], sm[h][1]), fmaxf(sm[h][2], sm[h][3]));
        float L = 0.f, A = 0.f;
#pragma unroll
        for (int wv = 0; wv < 4; wv++) {
            float mw = sm[h][wv];
            float f  = (mw == -CUDART_INF_F) ? 0.f : __expf(mw - M);
            L += sl[h][wv] * f;
            A += sa[h][wv][tid] * f;
        }
        int idx = ((b * NH_ + kv * 2 + h) * NSPLIT_ + s);
        g_pacc[(size_t)idx * HD_ + tid] = A;
        if (tid == 0) { g_pmax[idx] = M; g_psum[idx] = L; }
    }
}

// =====================================================================
// Kernel 4: combine splits -> g_attn[b, qh*HD + d]
// =====================================================================
__global__ void k_attn_combine() {
    const int bq = blockIdx.x;       // b*NH + qh
    const int tid = threadIdx.x;     // 128
    float M = -CUDART_INF_F;
#pragma unroll
    for (int s = 0; s < NSPLIT_; s++) M = fmaxf(M, g_pmax[bq * NSPLIT_ + s]);
    float L = 0.f, A = 0.f;
#pragma unroll
    for (int s = 0; s < NSPLIT_; s++) {
        float mw = g_pmax[bq * NSPLIT_ + s];
        float f  = (mw == -CUDART_INF_F) ? 0.f : __expf(mw - M);
        L += g_psum[bq * NSPLIT_ + s] * f;
        A += g_pacc[((size_t)bq * NSPLIT_ + s) * HD_ + tid] * f;
    }
    g_attn[bq * HD_ + tid] = A / L;  // ctx >= 1 so L > 0
}

// =====================================================================
// Kernel 5: output projection.  out[b,o] = attn[b,:] . o_w[o,:]
// =====================================================================
__global__ void k_oproj_gemv(const float* __restrict__ ow,
                             float* __restrict__ out) {
    const int o   = blockIdx.x;      // 2048 blocks
    const int tid = threadIdx.x;     // 128
    const float4* wr = reinterpret_cast<const float4*>(ow + (size_t)o * QSZ_);
    float acc[B_];
#pragma unroll
    for (int b = 0; b < B_; b++) acc[b] = 0.f;
    for (int j = tid; j < QSZ_ / 4; j += 128) {
        float4 w4 = wr[j];
#pragma unroll
        for (int b = 0; b < B_; b++) {
            float4 a4 = reinterpret_cast<const float4*>(g_attn + b * QSZ_)[j];
            acc[b] += w4.x * a4.x + w4.y * a4.y + w4.z * a4.z + w4.w * a4.w;
        }
    }
    __shared__ float red[4][B_];
    const int lane = tid & 31, wrp = tid >> 5;
#pragma unroll
    for (int b = 0; b < B_; b++) {
        float v = acc[b];
#pragma unroll
        for (int off = 16; off; off >>= 1) v += __shfl_xor_sync(0xffffffffu, v, off);
        if (lane == 0) red[wrp][b] = v;
    }
    __syncthreads();
    if (tid < B_)
        out[(size_t)tid * HID_ + o] =
            red[0][tid] + red[1][tid] + red[2][tid] + red[3][tid];
}

// =====================================================================
extern "C" void kernel_launch(void* const* d_in, const int* in_sizes, int n_in,
                              void* d_out, int out_size) {
    const float* hidden   = (const float*)d_in[0];
    const int*   positions= (const int*)  d_in[1];
    const float* qkv_w    = (const float*)d_in[2];
    const float* q_norm_w = (const float*)d_in[3];
    const float* k_norm_w = (const float*)d_in[4];
    const float* o_w      = (const float*)d_in[5];
    const float* cs_cache = (const float*)d_in[6];
    const float* k_cache  = (const float*)d_in[7];
    const float* v_cache  = (const float*)d_in[8];
    // d_in[9] = slot_mapping (derived internally, unused)
    const int*   btab     = (const int*)  d_in[10];
    const int*   ctx_lens = (const int*)  d_in[11];
    float* out = (float*)d_out;

    k_qkv_gemv<<<QKVSZ_, 128>>>(hidden, qkv_w);
    k_norm_rope<<<dim3(NH_ + 2 * NKV_, B_), 128>>>(q_norm_w, k_norm_w, cs_cache, positions);
    k_attn_split<<<dim3(NSPLIT_, NKV_, B_), 128>>>(k_cache, v_cache, btab, ctx_lens);
    k_attn_combine<<<B_ * NH_, 128>>>();
    k_oproj_gemv<<<HID_, 128>>>(o_w, out);
}

// round 4
// speedup vs baseline: 2.4215x; 1.1333x over previous
#include <cuda_runtime.h>
#include <math_constants.h>

// ----- problem constants -----
#define B_       16
#define HID_     2048
#define NH_      16
#define NKV_     8
#define HD_      128
#define BLK_     16
#define MAXB_    256
#define QSZ_     2048   // NH*HD
#define KVSZ_    1024   // NKV*HD
#define QKVSZ_   4096
#define NSPLIT_  16
#define CHUNK_   256    // LMAX/NSPLIT
#define TB_      8      // tokens per warp per mainloop iteration
#define SCALE_   0.08838834764831845f  // 128^-0.5
#define EPS_     1e-6f

// ----- scratch -----
__device__ float g_qkv [B_ * QKVSZ_];
__device__ float g_pmax[B_ * NH_ * NSPLIT_];
__device__ float g_psum[B_ * NH_ * NSPLIT_];
__device__ float g_pacc[B_ * NH_ * NSPLIT_ * HD_];
__device__ float g_attn[B_ * QSZ_];

__device__ __forceinline__ float4 shfl_xor_f4(float4 v, int m) {
    v.x = __shfl_xor_sync(0xffffffffu, v.x, m);
    v.y = __shfl_xor_sync(0xffffffffu, v.y, m);
    v.z = __shfl_xor_sync(0xffffffffu, v.z, m);
    v.w = __shfl_xor_sync(0xffffffffu, v.w, m);
    return v;
}

// =====================================================================
// Unified GEMV: y[b, o] = x[b,:] . w[o,:],  K = 2048 for both uses.
// Block = 128 threads = 4 warps; warp w owns batch rows [4w,4w+4);
// block owns 8 consecutive output rows. Each activation float4 is
// reused across all 8 weight rows (8x less L2 activation traffic).
// =====================================================================
__global__ void __launch_bounds__(128)
k_gemv8(const float* __restrict__ x, const float* __restrict__ w,
        float* __restrict__ y, int ostride) {
    const int o0   = blockIdx.x * 8;
    const int lane = threadIdx.x & 31, wrp = threadIdx.x >> 5;
    const int b0   = wrp * 4;
    const float4* xp = reinterpret_cast<const float4*>(x) + (size_t)b0 * 512;
    const float4* wp = reinterpret_cast<const float4*>(w) + (size_t)o0 * 512;

    float acc[4][8];
#pragma unroll
    for (int bb = 0; bb < 4; bb++)
#pragma unroll
        for (int r = 0; r < 8; r++) acc[bb][r] = 0.f;

#pragma unroll
    for (int it = 0; it < 16; it++) {
        const int j = lane + it * 32;
        float4 h4[4], w4[8];
#pragma unroll
        for (int bb = 0; bb < 4; bb++) h4[bb] = __ldg(xp + bb * 512 + j);
#pragma unroll
        for (int r = 0; r < 8; r++)   w4[r]  = __ldg(wp + r * 512 + j);
#pragma unroll
        for (int bb = 0; bb < 4; bb++)
#pragma unroll
            for (int r = 0; r < 8; r++) {
                acc[bb][r] += h4[bb].x * w4[r].x + h4[bb].y * w4[r].y
                            + h4[bb].z * w4[r].z + h4[bb].w * w4[r].w;
            }
    }
    // full warp reduction of each acc (all lanes end with the sum)
#pragma unroll
    for (int bb = 0; bb < 4; bb++)
#pragma unroll
        for (int r = 0; r < 8; r++) {
            float v = acc[bb][r];
#pragma unroll
            for (int off = 16; off; off >>= 1) v += __shfl_xor_sync(0xffffffffu, v, off);
            acc[bb][r] = v;
        }
    // predicated static writes: lane bb*8+r stores acc[bb][r]
#pragma unroll
    for (int bb = 0; bb < 4; bb++)
#pragma unroll
        for (int r = 0; r < 8; r++)
            if (lane == bb * 8 + r)
                y[(size_t)(b0 + bb) * ostride + o0 + r] = acc[bb][r];
}

// =====================================================================
// Fused attention: per-block norm+RoPE prologue + split-KV flash decode.
// grid (NSPLIT, NKV, B), 128 threads (4 warps).
// Prologue: warp 0->q(2kv), warp 1->q(2kv+1), warp 2->k, warp 3->v.
// =====================================================================
__global__ void __launch_bounds__(128)
k_attn_split(const float* __restrict__ kc,
             const float* __restrict__ vc,
             const int*   __restrict__ btab,
             const int*   __restrict__ ctx_lens,
             const float* __restrict__ qnw,
             const float* __restrict__ knw,
             const float* __restrict__ cs_cache,
             const int*   __restrict__ positions) {
    const int s  = blockIdx.x, kv = blockIdx.y, b = blockIdx.z;
    const int tid = threadIdx.x, lane = tid & 31, wrp = tid >> 5;
    const int ctx   = ctx_lens[b];
    const int start = s * CHUNK_;
    const int end   = min(start + CHUNK_, ctx);

    __shared__ float s_head[4][HD_];   // q0, q1, k_new, v_new

    // ---- prologue: RMSNorm + RoPE for this block's heads ----
    {
        const float* base = g_qkv + b * QKVSZ_;
        const float* src;
        const float* nw = nullptr;
        if      (wrp == 0) { src = base + (2 * kv    ) * HD_;          nw = qnw; }
        else if (wrp == 1) { src = base + (2 * kv + 1) * HD_;          nw = qnw; }
        else if (wrp == 2) { src = base + QSZ_ + kv * HD_;             nw = knw; }
        else               { src = base + QSZ_ + KVSZ_ + kv * HD_; }
        float4 x = reinterpret_cast<const float4*>(src)[lane];
        if (wrp < 3) {
            float ss = x.x * x.x + x.y * x.y + x.z * x.z + x.w * x.w;
#pragma unroll
            for (int off = 16; off; off >>= 1) ss += __shfl_xor_sync(0xffffffffu, ss, off);
            float rn = rsqrtf(ss * (1.f / HD_) + EPS_);
            const float4 nw4 = reinterpret_cast<const float4*>(nw)[lane];
            x.x *= rn * nw4.x;  x.y *= rn * nw4.y;
            x.z *= rn * nw4.z;  x.w *= rn * nw4.w;
            // RoPE: pair dim d with d+64 via shfl xor 16
            float4 p = shfl_xor_f4(x, 16);
            const float* cs = cs_cache + (size_t)positions[b] * HD_;
            const int d0 = (lane < 16) ? 4 * lane : 4 * lane - 64;
            const float4 c4 = *reinterpret_cast<const float4*>(cs + d0);
            const float4 s4 = *reinterpret_cast<const float4*>(cs + 64 + d0);
            if (lane < 16) {
                x.x = x.x * c4.x - p.x * s4.x;  x.y = x.y * c4.y - p.y * s4.y;
                x.z = x.z * c4.z - p.z * s4.z;  x.w = x.w * c4.w - p.w * s4.w;
            } else {
                x.x = x.x * c4.x + p.x * s4.x;  x.y = x.y * c4.y + p.y * s4.y;
                x.z = x.z * c4.z + p.z * s4.z;  x.w = x.w * c4.w + p.w * s4.w;
            }
        }
        reinterpret_cast<float4*>(s_head[wrp])[lane] = x;
    }
    __syncthreads();

    const float4 q0 = reinterpret_cast<const float4*>(s_head[0])[lane];
    const float4 q1 = reinterpret_cast<const float4*>(s_head[1])[lane];

    float m0 = -CUDART_INF_F, m1 = -CUDART_INF_F, l0 = 0.f, l1 = 0.f;
    float a0[4] = {0, 0, 0, 0}, a1[4] = {0, 0, 0, 0};
    const int* btr = btab + b * MAXB_;

    for (int base = start + wrp * TB_; base < end; base += 4 * TB_) {
        float4 k4[TB_], v4[TB_];
        float s0[TB_], s1[TB_];
#pragma unroll
        for (int i = 0; i < TB_; i++) {
            int t = base + i;
            if (t < end) {
                if (t == ctx - 1) {
                    k4[i] = reinterpret_cast<const float4*>(s_head[2])[lane];
                    v4[i] = reinterpret_cast<const float4*>(s_head[3])[lane];
                } else {
                    int slot = btr[t >> 4] * BLK_ + (t & (BLK_ - 1));
                    size_t off = ((size_t)slot * NKV_ + kv) * HD_;
                    k4[i] = __ldcs(reinterpret_cast<const float4*>(kc + off) + lane);
                    v4[i] = __ldcs(reinterpret_cast<const float4*>(vc + off) + lane);
                }
            } else {
                k4[i] = make_float4(0.f, 0.f, 0.f, 0.f);
                v4[i] = make_float4(0.f, 0.f, 0.f, 0.f);
            }
        }
#pragma unroll
        for (int i = 0; i < TB_; i++) {
            s0[i] = q0.x * k4[i].x + q0.y * k4[i].y + q0.z * k4[i].z + q0.w * k4[i].w;
            s1[i] = q1.x * k4[i].x + q1.y * k4[i].y + q1.z * k4[i].z + q1.w * k4[i].w;
        }
#pragma unroll
        for (int off = 16; off; off >>= 1) {
#pragma unroll
            for (int i = 0; i < TB_; i++) {
                s0[i] += __shfl_xor_sync(0xffffffffu, s0[i], off);
                s1[i] += __shfl_xor_sync(0xffffffffu, s1[i], off);
            }
        }
        float bm0 = -CUDART_INF_F, bm1 = -CUDART_INF_F;
#pragma unroll
        for (int i = 0; i < TB_; i++) {
            if (base + i < end) { s0[i] *= SCALE_; s1[i] *= SCALE_; }
            else                { s0[i] = -CUDART_INF_F; s1[i] = -CUDART_INF_F; }
            bm0 = fmaxf(bm0, s0[i]);
            bm1 = fmaxf(bm1, s1[i]);
        }
        float nm0 = fmaxf(m0, bm0), nm1 = fmaxf(m1, bm1);
        float f0 = __expf(m0 - nm0), f1 = __expf(m1 - nm1);
        l0 *= f0;  l1 *= f1;
#pragma unroll
        for (int j = 0; j < 4; j++) { a0[j] *= f0; a1[j] *= f1; }
#pragma unroll
        for (int i = 0; i < TB_; i++) {
            float p0 = __expf(s0[i] - nm0);
            float p1 = __expf(s1[i] - nm1);
            l0 += p0;  l1 += p1;
            a0[0] += p0 * v4[i].x;  a1[0] += p1 * v4[i].x;
            a0[1] += p0 * v4[i].y;  a1[1] += p1 * v4[i].y;
            a0[2] += p0 * v4[i].z;  a1[2] += p1 * v4[i].z;
            a0[3] += p0 * v4[i].w;  a1[3] += p1 * v4[i].w;
        }
        m0 = nm0;  m1 = nm1;
    }

    // combine the 4 warps
    __shared__ float sm[2][4], sl[2][4], sa[2][4][HD_];
    if (lane == 0) { sm[0][wrp] = m0; sm[1][wrp] = m1; sl[0][wrp] = l0; sl[1][wrp] = l1; }
#pragma unroll
    for (int j = 0; j < 4; j++) {
        sa[0][wrp][lane * 4 + j] = a0[j];
        sa[1][wrp][lane * 4 + j] = a1[j];
    }
    __syncthreads();
#pragma unroll
    for (int h = 0; h < 2; h++) {
        float M = fmaxf(fmaxf(sm[h][0], sm[h][1]), fmaxf(sm[h][2], sm[h][3]));
        float L = 0.f, A = 0.f;
#pragma unroll
        for (int wv = 0; wv < 4; wv++) {
            float mw = sm[h][wv];
            float f  = (mw == -CUDART_INF_F) ? 0.f : __expf(mw - M);
            L += sl[h][wv] * f;
            A += sa[h][wv][tid] * f;
        }
        int idx = ((b * NH_ + kv * 2 + h) * NSPLIT_ + s);
        g_pacc[(size_t)idx * HD_ + tid] = A;
        if (tid == 0) { g_pmax[idx] = M; g_psum[idx] = L; }
    }
}

// =====================================================================
// Combine splits: one warp per (b, qhead). grid 64 x 128 threads.
// =====================================================================
__global__ void __launch_bounds__(128) k_attn_combine() {
    const int bq   = blockIdx.x * 4 + (threadIdx.x >> 5);
    const int lane = threadIdx.x & 31;
    float mv = (lane < NSPLIT_) ? g_pmax[bq * NSPLIT_ + lane] : -CUDART_INF_F;
    float M = mv;
#pragma unroll
    for (int off = 16; off; off >>= 1) M = fmaxf(M, __shfl_xor_sync(0xffffffffu, M, off));
    float f  = (lane < NSPLIT_) ? __expf(mv - M) : 0.f;   // exp(-inf - M) = 0
    float lv = (lane < NSPLIT_) ? g_psum[bq * NSPLIT_ + lane] : 0.f;
    float L = lv * f;
#pragma unroll
    for (int off = 16; off; off >>= 1) L += __shfl_xor_sync(0xffffffffu, L, off);
    float4 A = make_float4(0.f, 0.f, 0.f, 0.f);
#pragma unroll
    for (int s = 0; s < NSPLIT_; s++) {
        float fs = __shfl_sync(0xffffffffu, f, s);
        float4 p = reinterpret_cast<const float4*>(
                       g_pacc + ((size_t)bq * NSPLIT_ + s) * HD_)[lane];
        A.x += fs * p.x;  A.y += fs * p.y;  A.z += fs * p.z;  A.w += fs * p.w;
    }
    const float inv = 1.f / L;
    A.x *= inv;  A.y *= inv;  A.z *= inv;  A.w *= inv;
    reinterpret_cast<float4*>(g_attn + bq * HD_)[lane] = A;
}

// =====================================================================
extern "C" void kernel_launch(void* const* d_in, const int* in_sizes, int n_in,
                              void* d_out, int out_size) {
    const float* hidden   = (const float*)d_in[0];
    const int*   positions= (const int*)  d_in[1];
    const float* qkv_w    = (const float*)d_in[2];
    const float* q_norm_w = (const float*)d_in[3];
    const float* k_norm_w = (const float*)d_in[4];
    const float* o_w      = (const float*)d_in[5];
    const float* cs_cache = (const float*)d_in[6];
    const float* k_cache  = (const float*)d_in[7];
    const float* v_cache  = (const float*)d_in[8];
    // d_in[9] = slot_mapping (derived internally, unused)
    const int*   btab     = (const int*)  d_in[10];
    const int*   ctx_lens = (const int*)  d_in[11];
    float* out = (float*)d_out;

    float* d_qkv;  cudaGetSymbolAddress((void**)&d_qkv,  g_qkv);
    float* d_attn; cudaGetSymbolAddress((void**)&d_attn, g_attn);

    k_gemv8<<<QKVSZ_ / 8, 128>>>(hidden, qkv_w, d_qkv, QKVSZ_);
    k_attn_split<<<dim3(NSPLIT_, NKV_, B_), 128>>>(k_cache, v_cache, btab, ctx_lens,
                                                   q_norm_w, k_norm_w, cs_cache, positions);
    k_attn_combine<<<B_ * NH_ / 4, 128>>>();
    k_gemv8<<<HID_ / 8, 128>>>(d_attn, o_w, out, HID_);
}